// round 11
// baseline (speedup 1.0000x reference)
#include <cuda_runtime.h>
#include <cstdint>

#define NTOK  4096
#define CDIM  256
#define HIDD  64
#define BATCH 4

// Projection scratch (tf32-rounded): q,k: [src][b][n][64]; v TRANSPOSED: [src][b][c][m]
__device__ float g_q[2][BATCH][NTOK][HIDD];
__device__ float g_k[2][BATCH][NTOK][HIDD];
__device__ float g_vt[2][BATCH][CDIM][NTOK];

// ---------------------------------------------------------------------------
// helpers
// ---------------------------------------------------------------------------
__device__ __forceinline__ float to_tf32(float x) {
    uint32_t u;
    asm("cvt.rna.tf32.f32 %0, %1;" : "=r"(u) : "f"(x));
    return __uint_as_float(u);
}

__device__ __forceinline__ void mma_tf32(float c[4],
                                         uint32_t a0, uint32_t a1, uint32_t a2, uint32_t a3,
                                         uint32_t b0, uint32_t b1) {
    asm volatile(
        "mma.sync.aligned.m16n8k8.row.col.f32.tf32.tf32.f32 "
        "{%0,%1,%2,%3}, {%4,%5,%6,%7}, {%8,%9}, {%0,%1,%2,%3};\n"
        : "+f"(c[0]), "+f"(c[1]), "+f"(c[2]), "+f"(c[3])
        : "r"(a0), "r"(a1), "r"(a2), "r"(a3), "r"(b0), "r"(b1));
}

// fast exp on the FMA pipe
__device__ __forceinline__ float fexp(float x) {
    float t = x * 1.4426950408889634f;
    t = fmaxf(t, -126.0f);
    float fi = t + 12582912.0f;
    int   ii = __float_as_int(fi) - 0x4B400000;
    float fr = t - (fi - 12582912.0f);
    float u  = fr * 0.6931471805599453f;
    float p  = 8.3333337e-3f;
    p = fmaf(p, u, 4.1666668e-2f);
    p = fmaf(p, u, 0.16666667f);
    p = fmaf(p, u, 0.5f);
    p = fmaf(p, u, 1.0f);
    p = fmaf(p, u, 1.0f);
    return __int_as_float(__float_as_int(p) + (ii << 23));
}

// ---------------------------------------------------------------------------
// Projection via tf32 mma (unchanged, passing)
// ---------------------------------------------------------------------------
__global__ __launch_bounds__(256) void proj_kernel(
    const float* __restrict__ x1, const float* __restrict__ x2,
    const float* __restrict__ Wq, const float* __restrict__ bq,
    const float* __restrict__ Wk, const float* __restrict__ bk,
    const float* __restrict__ Wv, const float* __restrict__ bv)
{
    int ntile = blockIdx.x;
    int otile = blockIdx.y;
    int src   = blockIdx.z >> 2;
    int b     = blockIdx.z & 3;
    const float* x = src ? x2 : x1;

    const float* W; const float* bias; int oofs;
    if (otile == 0)      { W = Wq; bias = bq; oofs = 0; }
    else if (otile == 1) { W = Wk; bias = bk; oofs = 0; }
    else                 { W = Wv; bias = bv; oofs = (otile - 2) * 64; }

    __shared__ float Ws[64][68];
    __shared__ float Xs[64][72];

    int t    = threadIdx.x;
    int warp = t >> 5, lane = t & 31;
    int g    = lane >> 2, tig = lane & 3;
    int wr   = warp >> 1, wc = warp & 1;
    int n0   = ntile * 64;

    float acc[4][4] = {};
    const float4* W4 = (const float4*)W;

    for (int cc = 0; cc < CDIM; cc += 64) {
        for (int i = t; i < 1024; i += 256) {
            int r = i >> 4, kq = i & 15;
            float4 w = W4[(size_t)(oofs + r) * 64 + (cc >> 2) + kq];
            Ws[r][kq * 4 + 0] = to_tf32(w.x);
            Ws[r][kq * 4 + 1] = to_tf32(w.y);
            Ws[r][kq * 4 + 2] = to_tf32(w.z);
            Ws[r][kq * 4 + 3] = to_tf32(w.w);
        }
        const float4* X4 = (const float4*)x;
        for (int i = t; i < 1024; i += 256) {
            int r = i >> 4, cq = i & 15;
            float4 v = X4[(size_t)(b * CDIM + cc + r) * (NTOK / 4) + (n0 >> 2) + cq];
            Xs[r][cq * 4 + 0] = to_tf32(v.x);
            Xs[r][cq * 4 + 1] = to_tf32(v.y);
            Xs[r][cq * 4 + 2] = to_tf32(v.z);
            Xs[r][cq * 4 + 3] = to_tf32(v.w);
        }
        __syncthreads();
        int ob = wr * 16;
        #pragma unroll
        for (int kk = 0; kk < 8; kk++) {
            int k0 = kk * 8;
            uint32_t a0 = __float_as_uint(Ws[ob + g][k0 + tig]);
            uint32_t a1 = __float_as_uint(Ws[ob + g + 8][k0 + tig]);
            uint32_t a2 = __float_as_uint(Ws[ob + g][k0 + tig + 4]);
            uint32_t a3 = __float_as_uint(Ws[ob + g + 8][k0 + tig + 4]);
            #pragma unroll
            for (int j = 0; j < 4; j++) {
                int nb = wc * 32 + j * 8;
                uint32_t b0 = __float_as_uint(Xs[k0 + tig][nb + g]);
                uint32_t b1 = __float_as_uint(Xs[k0 + tig + 4][nb + g]);
                mma_tf32(acc[j], a0, a1, a2, a3, b0, b1);
            }
        }
        __syncthreads();
    }

    float* stage = &Ws[0][0];
    int o0 = wr * 16 + g, o1 = o0 + 8;
    float bz0 = bias[oofs + o0], bz1 = bias[oofs + o1];

    if (otile < 2) {
        #pragma unroll
        for (int j = 0; j < 4; j++) {
            int nl = wc * 32 + j * 8 + tig * 2;
            stage[(nl)     * 64 + o0] = to_tf32(acc[j][0] + bz0);
            stage[(nl + 1) * 64 + o0] = to_tf32(acc[j][1] + bz0);
            stage[(nl)     * 64 + o1] = to_tf32(acc[j][2] + bz1);
            stage[(nl + 1) * 64 + o1] = to_tf32(acc[j][3] + bz1);
        }
        __syncthreads();
        float* outb = (otile == 0) ? &g_q[src][b][0][0] : &g_k[src][b][0][0];
        for (int i = t; i < 4096; i += 256) {
            int nl = i >> 6, o = i & 63;
            outb[(size_t)(n0 + nl) * 64 + o] = stage[nl * 64 + o];
        }
    } else {
        #pragma unroll
        for (int j = 0; j < 4; j++) {
            int nl = wc * 32 + j * 8 + tig * 2;
            stage[o0 * 64 + nl]     = to_tf32(acc[j][0] + bz0);
            stage[o0 * 64 + nl + 1] = to_tf32(acc[j][1] + bz0);
            stage[o1 * 64 + nl]     = to_tf32(acc[j][2] + bz1);
            stage[o1 * 64 + nl + 1] = to_tf32(acc[j][3] + bz1);
        }
        __syncthreads();
        float* outb = &g_vt[src][b][oofs][0];
        for (int i = t; i < 4096; i += 256) {
            int o = i >> 6, nl = i & 63;
            outb[(size_t)o * NTOK + n0 + nl] = stage[o * 64 + nl];
        }
    }
}

// ---------------------------------------------------------------------------
// Flash cross-attention, tf32 mma, O^T = V^T P^T.
// grid (N/64, B, 2), block 256, 2 CTAs/SM.
// Ownership-restructured: V^T rows are warp-private (copy+consume by same
// warp); K rows duplicate-written by every reader warp (identical values, so
// the write-write race is benign and each warp reads its own stores).
// Only P crosses warps -> exactly 2 __syncthreads per iteration:
//   [PV_{i-1}] copyK_i copyV_i S_i  |sync1|  softmax->P_i  |sync2|  PV_i
// ---------------------------------------------------------------------------
#define PADH 68
#define SM_VT   0                        // 256 x 68 (warp-private V^T rows; staging)
#define SM_K    (256 * PADH)             // 64 x 68  K tile (dup-written)
#define SM_P    (SM_K + 64 * PADH)       // 64 x 68  P tile
#define SM_RS   (SM_P + 64 * PADH)       // 128
#define SM_INV  (SM_RS + 128)            // 64
#define ATTN_SMEM_FLOATS (SM_INV + 64)   // 26304 floats = 105216 B

__global__ __launch_bounds__(256, 2) void attn_kernel(
    const float* __restrict__ x1, const float* __restrict__ x2,
    const float* __restrict__ gamma_p, float* __restrict__ out)
{
    int qtile = blockIdx.x, b = blockIdx.y, dir = blockIdx.z;
    int srckv = dir ^ 1;
    const float* xq = dir ? x2 : x1;
    int n0 = qtile * 64;

    extern __shared__ float sm[];
    float* Vt  = sm + SM_VT;
    float* Ksm = sm + SM_K;
    float* Psm = sm + SM_P;
    float* rs  = sm + SM_RS;
    float* inv = sm + SM_INV;

    int t    = threadIdx.x;
    int warp = t >> 5, lane = t & 31;
    int g    = lane >> 2, tig = lane & 3;
    int wr   = warp >> 1, wc = warp & 1;
    int qb   = wr * 16;        // S-phase q-row base (wr 0..3)
    int cb   = warp * 32;      // PV-phase c-row base (warp-private V rows)

    const float4* kg4  = (const float4*)&g_k[srckv][b][0][0];
    const float4* vtg4 = (const float4*)&g_vt[srckv][b][0][0];

    // ---- prologue: stage Q in Vt area, lift fragments to registers ----
    {
        const float4* qg4 = (const float4*)&g_q[dir][b][n0][0];
        #pragma unroll
        for (int j = 0; j < 4; j++) {
            int i = t + 256 * j;
            int r = i >> 4, cq = i & 15;
            *(float4*)&Vt[r * PADH + cq * 4] = qg4[i];
        }
    }
    if (t < 128) rs[t] = 0.f;
    __syncthreads();

    float qf[8][4];
    #pragma unroll
    for (int kk = 0; kk < 8; kk++) {
        int k0 = kk * 8;
        qf[kk][0] = Vt[(qb + g)     * PADH + k0 + tig];
        qf[kk][1] = Vt[(qb + g + 8) * PADH + k0 + tig];
        qf[kk][2] = Vt[(qb + g)     * PADH + k0 + tig + 4];
        qf[kk][3] = Vt[(qb + g + 8) * PADH + k0 + tig + 4];
    }
    float oacc[16][4] = {};
    __syncthreads();   // Q fragments lifted; Vt free for V tiles

    for (int it = 0; it < NTOK / 64; it++) {
        // ---- copy K_it rows [wc*32, wc*32+32): duplicate-written by all 4
        //      warps sharing this m-half; each warp reads only its own stores.
        {
            const float4* ksrc = kg4 + (size_t)it * 1024 + wc * 32 * 16;
            #pragma unroll
            for (int j = 0; j < 16; j++) {
                int idx = j * 32 + lane;
                int r = idx >> 4, c4 = idx & 15;
                *(float4*)&Ksm[(wc * 32 + r) * PADH + c4 * 4] = ksrc[r * 16 + c4];
            }
        }
        // ---- copy V^T_it rows [cb, cb+32): strictly warp-private ----
        {
            #pragma unroll
            for (int j = 0; j < 16; j++) {
                int idx = j * 32 + lane;
                int r = idx >> 4, mq = idx & 15;
                *(float4*)&Vt[(cb + r) * PADH + mq * 4] =
                    vtg4[(size_t)(cb + r) * 1024 + it * 16 + mq];
            }
        }

        // ---- S = Q K^T (reads own K stores; Q in regs) ----
        float sf[4][4] = {};
        #pragma unroll
        for (int kk = 0; kk < 8; kk++) {
            int k0 = kk * 8;
            uint32_t a0 = __float_as_uint(qf[kk][0]);
            uint32_t a1 = __float_as_uint(qf[kk][1]);
            uint32_t a2 = __float_as_uint(qf[kk][2]);
            uint32_t a3 = __float_as_uint(qf[kk][3]);
            #pragma unroll
            for (int nb = 0; nb < 4; nb++) {
                int m = wc * 32 + nb * 8;
                uint32_t b0 = __float_as_uint(Ksm[(m + g) * PADH + k0 + tig]);
                uint32_t b1 = __float_as_uint(Ksm[(m + g) * PADH + k0 + tig + 4]);
                mma_tf32(sf[nb], a0, a1, a2, a3, b0, b1);
            }
        }
        __syncthreads();   // #1: all PV_{it-1} reads of P done -> safe to overwrite P

        // ---- no-max softmax; P -> Psm ----
        {
            float ps0 = 0.f, ps1 = 0.f;
            #pragma unroll
            for (int nb = 0; nb < 4; nb++) {
                float p0 = fexp(sf[nb][0]);
                float p1 = fexp(sf[nb][1]);
                float p2 = fexp(sf[nb][2]);
                float p3 = fexp(sf[nb][3]);
                ps0 += p0 + p1;
                ps1 += p2 + p3;
                int col = wc * 32 + nb * 8 + tig * 2;
                Psm[(qb + g)     * PADH + col]     = to_tf32(p0);
                Psm[(qb + g)     * PADH + col + 1] = to_tf32(p1);
                Psm[(qb + g + 8) * PADH + col]     = to_tf32(p2);
                Psm[(qb + g + 8) * PADH + col + 1] = to_tf32(p3);
            }
            ps0 += __shfl_xor_sync(0xffffffffu, ps0, 1);
            ps0 += __shfl_xor_sync(0xffffffffu, ps0, 2);
            ps1 += __shfl_xor_sync(0xffffffffu, ps1, 1);
            ps1 += __shfl_xor_sync(0xffffffffu, ps1, 2);
            if (tig == 0) {
                rs[wc * 64 + qb + g]     += ps0;
                rs[wc * 64 + qb + g + 8] += ps1;
            }
        }
        __syncthreads();   // #2: P visible to all warps

        // ---- O^T += V^T P^T, kk-outer (B fragments shared by both c-subtiles) ----
        #pragma unroll
        for (int kk = 0; kk < 8; kk++) {
            int k0 = kk * 8;
            uint32_t A0[4], A1[4];
            A0[0] = __float_as_uint(Vt[(cb + g)      * PADH + k0 + tig]);
            A0[1] = __float_as_uint(Vt[(cb + g + 8)  * PADH + k0 + tig]);
            A0[2] = __float_as_uint(Vt[(cb + g)      * PADH + k0 + tig + 4]);
            A0[3] = __float_as_uint(Vt[(cb + g + 8)  * PADH + k0 + tig + 4]);
            A1[0] = __float_as_uint(Vt[(cb + g + 16) * PADH + k0 + tig]);
            A1[1] = __float_as_uint(Vt[(cb + g + 24) * PADH + k0 + tig]);
            A1[2] = __float_as_uint(Vt[(cb + g + 16) * PADH + k0 + tig + 4]);
            A1[3] = __float_as_uint(Vt[(cb + g + 24) * PADH + k0 + tig + 4]);
            #pragma unroll
            for (int nb = 0; nb < 8; nb++) {
                int q = nb * 8;
                uint32_t b0 = __float_as_uint(Psm[(q + g) * PADH + k0 + tig]);
                uint32_t b1 = __float_as_uint(Psm[(q + g) * PADH + k0 + tig + 4]);
                mma_tf32(oacc[nb],     A0[0], A0[1], A0[2], A0[3], b0, b1);
                mma_tf32(oacc[8 + nb], A1[0], A1[1], A1[2], A1[3], b0, b1);
            }
        }
        // no barrier here: next iter's K dup-writes are self-read, V rows are
        // warp-private, and P is protected by sync #1 of the next iteration.
    }

    // ---- epilogue ----
    __syncthreads();
    if (t < 64) inv[t] = 1.f / (rs[t] + rs[64 + t]);

    float* stage = Vt;   // [c][q] stride 65, rows cb.. are warp-private
    #pragma unroll
    for (int mt2 = 0; mt2 < 2; mt2++) {
        int crow = cb + mt2 * 16;
        #pragma unroll
        for (int nb = 0; nb < 8; nb++) {
            int q = nb * 8 + tig * 2;
            stage[(crow + g)     * 65 + q]     = oacc[mt2 * 8 + nb][0];
            stage[(crow + g)     * 65 + q + 1] = oacc[mt2 * 8 + nb][1];
            stage[(crow + g + 8) * 65 + q]     = oacc[mt2 * 8 + nb][2];
            stage[(crow + g + 8) * 65 + q + 1] = oacc[mt2 * 8 + nb][3];
        }
    }
    __syncthreads();

    float gm = gamma_p[0];
    size_t obase = ((size_t)(dir * BATCH + b)) * CDIM * NTOK;
    const float* xb = xq + (size_t)b * CDIM * NTOK;
    for (int i = t; i < 64 * 256; i += 256) {
        int c = i >> 6, nl = i & 63;
        size_t idx = (size_t)c * NTOK + n0 + nl;
        out[obase + idx] = xb[idx] + gm * inv[nl] * stage[c * 65 + nl];
    }
}

extern "C" void kernel_launch(void* const* d_in, const int* in_sizes, int n_in,
                              void* d_out, int out_size)
{
    const float* x1    = (const float*)d_in[0];
    const float* x2    = (const float*)d_in[1];
    const float* Wq    = (const float*)d_in[2];
    const float* bq    = (const float*)d_in[3];
    const float* Wk    = (const float*)d_in[4];
    const float* bk    = (const float*)d_in[5];
    const float* Wv    = (const float*)d_in[6];
    const float* bv    = (const float*)d_in[7];
    const float* gamma = (const float*)d_in[8];
    float* out = (float*)d_out;
    (void)in_sizes; (void)n_in; (void)out_size;

    size_t attn_smem = (size_t)ATTN_SMEM_FLOATS * sizeof(float);
    cudaFuncSetAttribute(attn_kernel, cudaFuncAttributeMaxDynamicSharedMemorySize,
                         (int)attn_smem);

    proj_kernel<<<dim3(NTOK / 64, 6, 2 * BATCH), 256>>>(x1, x2, Wq, bq, Wk, bk, Wv, bv);
    attn_kernel<<<dim3(NTOK / 64, BATCH, 2), 256, attn_smem>>>(x1, x2, gamma, out);
}

// round 12
// speedup vs baseline: 3.1831x; 3.1831x over previous
#include <cuda_runtime.h>
#include <cuda_fp16.h>
#include <cstdint>

#define NTOK  4096
#define CDIM  256
#define HIDD  64
#define BATCH 4

// Projection scratch, fp16: q,k: [src][b][n][64]; v TRANSPOSED: [src][b][c][m]
__device__ __half g_qh[2][BATCH][NTOK][HIDD];
__device__ __half g_kh[2][BATCH][NTOK][HIDD];
__device__ __half g_vth[2][BATCH][CDIM][NTOK];

// ---------------------------------------------------------------------------
// helpers
// ---------------------------------------------------------------------------
__device__ __forceinline__ float to_tf32(float x) {
    uint32_t u;
    asm("cvt.rna.tf32.f32 %0, %1;" : "=r"(u) : "f"(x));
    return __uint_as_float(u);
}

__device__ __forceinline__ void mma_tf32(float c[4],
                                         uint32_t a0, uint32_t a1, uint32_t a2, uint32_t a3,
                                         uint32_t b0, uint32_t b1) {
    asm volatile(
        "mma.sync.aligned.m16n8k8.row.col.f32.tf32.tf32.f32 "
        "{%0,%1,%2,%3}, {%4,%5,%6,%7}, {%8,%9}, {%0,%1,%2,%3};\n"
        : "+f"(c[0]), "+f"(c[1]), "+f"(c[2]), "+f"(c[3])
        : "r"(a0), "r"(a1), "r"(a2), "r"(a3), "r"(b0), "r"(b1));
}

__device__ __forceinline__ void mma_fp16(float c[4],
                                         uint32_t a0, uint32_t a1, uint32_t a2, uint32_t a3,
                                         uint32_t b0, uint32_t b1) {
    asm volatile(
        "mma.sync.aligned.m16n8k16.row.col.f32.f16.f16.f32 "
        "{%0,%1,%2,%3}, {%4,%5,%6,%7}, {%8,%9}, {%0,%1,%2,%3};\n"
        : "+f"(c[0]), "+f"(c[1]), "+f"(c[2]), "+f"(c[3])
        : "r"(a0), "r"(a1), "r"(a2), "r"(a3), "r"(b0), "r"(b1));
}

// fast exp on the FMA pipe
__device__ __forceinline__ float fexp(float x) {
    float t = x * 1.4426950408889634f;
    t = fmaxf(t, -126.0f);
    float fi = t + 12582912.0f;
    int   ii = __float_as_int(fi) - 0x4B400000;
    float fr = t - (fi - 12582912.0f);
    float u  = fr * 0.6931471805599453f;
    float p  = 8.3333337e-3f;
    p = fmaf(p, u, 4.1666668e-2f);
    p = fmaf(p, u, 0.16666667f);
    p = fmaf(p, u, 0.5f);
    p = fmaf(p, u, 1.0f);
    p = fmaf(p, u, 1.0f);
    return __int_as_float(__float_as_int(p) + (ii << 23));
}

__device__ __forceinline__ uint32_t h2_of(float a, float b) {
    __half2 h = __floats2half2_rn(a, b);
    return *(uint32_t*)&h;
}

// ---------------------------------------------------------------------------
// Projection via tf32 mma (R9 core, passing) — epilogue now emits fp16.
// ---------------------------------------------------------------------------
__global__ __launch_bounds__(256) void proj_kernel(
    const float* __restrict__ x1, const float* __restrict__ x2,
    const float* __restrict__ Wq, const float* __restrict__ bq,
    const float* __restrict__ Wk, const float* __restrict__ bk,
    const float* __restrict__ Wv, const float* __restrict__ bv)
{
    int ntile = blockIdx.x;
    int otile = blockIdx.y;
    int src   = blockIdx.z >> 2;
    int b     = blockIdx.z & 3;
    const float* x = src ? x2 : x1;

    const float* W; const float* bias; int oofs;
    if (otile == 0)      { W = Wq; bias = bq; oofs = 0; }
    else if (otile == 1) { W = Wk; bias = bk; oofs = 0; }
    else                 { W = Wv; bias = bv; oofs = (otile - 2) * 64; }

    __shared__ float Ws[64][68];
    __shared__ float Xs[64][72];

    int t    = threadIdx.x;
    int warp = t >> 5, lane = t & 31;
    int g    = lane >> 2, tig = lane & 3;
    int wr   = warp >> 1, wc = warp & 1;
    int n0   = ntile * 64;

    float acc[4][4] = {};
    const float4* W4 = (const float4*)W;

    for (int cc = 0; cc < CDIM; cc += 64) {
        for (int i = t; i < 1024; i += 256) {
            int r = i >> 4, kq = i & 15;
            float4 w = W4[(size_t)(oofs + r) * 64 + (cc >> 2) + kq];
            Ws[r][kq * 4 + 0] = to_tf32(w.x);
            Ws[r][kq * 4 + 1] = to_tf32(w.y);
            Ws[r][kq * 4 + 2] = to_tf32(w.z);
            Ws[r][kq * 4 + 3] = to_tf32(w.w);
        }
        const float4* X4 = (const float4*)x;
        for (int i = t; i < 1024; i += 256) {
            int r = i >> 4, cq = i & 15;
            float4 v = X4[(size_t)(b * CDIM + cc + r) * (NTOK / 4) + (n0 >> 2) + cq];
            Xs[r][cq * 4 + 0] = to_tf32(v.x);
            Xs[r][cq * 4 + 1] = to_tf32(v.y);
            Xs[r][cq * 4 + 2] = to_tf32(v.z);
            Xs[r][cq * 4 + 3] = to_tf32(v.w);
        }
        __syncthreads();
        int ob = wr * 16;
        #pragma unroll
        for (int kk = 0; kk < 8; kk++) {
            int k0 = kk * 8;
            uint32_t a0 = __float_as_uint(Ws[ob + g][k0 + tig]);
            uint32_t a1 = __float_as_uint(Ws[ob + g + 8][k0 + tig]);
            uint32_t a2 = __float_as_uint(Ws[ob + g][k0 + tig + 4]);
            uint32_t a3 = __float_as_uint(Ws[ob + g + 8][k0 + tig + 4]);
            #pragma unroll
            for (int j = 0; j < 4; j++) {
                int nb = wc * 32 + j * 8;
                uint32_t b0 = __float_as_uint(Xs[k0 + tig][nb + g]);
                uint32_t b1 = __float_as_uint(Xs[k0 + tig + 4][nb + g]);
                mma_tf32(acc[j], a0, a1, a2, a3, b0, b1);
            }
        }
        __syncthreads();
    }

    float* stage = &Ws[0][0];
    int o0 = wr * 16 + g, o1 = o0 + 8;
    float bz0 = bias[oofs + o0], bz1 = bias[oofs + o1];

    if (otile < 2) {
        #pragma unroll
        for (int j = 0; j < 4; j++) {
            int nl = wc * 32 + j * 8 + tig * 2;
            stage[(nl)     * 64 + o0] = acc[j][0] + bz0;
            stage[(nl + 1) * 64 + o0] = acc[j][1] + bz0;
            stage[(nl)     * 64 + o1] = acc[j][2] + bz1;
            stage[(nl + 1) * 64 + o1] = acc[j][3] + bz1;
        }
        __syncthreads();
        __half* outb = (otile == 0) ? &g_qh[src][b][0][0] : &g_kh[src][b][0][0];
        for (int i = t; i < 4096; i += 256) {
            int nl = i >> 6, o = i & 63;
            outb[(size_t)(n0 + nl) * 64 + o] = __float2half_rn(stage[nl * 64 + o]);
        }
    } else {
        #pragma unroll
        for (int j = 0; j < 4; j++) {
            int nl = wc * 32 + j * 8 + tig * 2;
            stage[o0 * 64 + nl]     = acc[j][0] + bz0;
            stage[o0 * 64 + nl + 1] = acc[j][1] + bz0;
            stage[o1 * 64 + nl]     = acc[j][2] + bz1;
            stage[o1 * 64 + nl + 1] = acc[j][3] + bz1;
        }
        __syncthreads();
        __half* outb = &g_vth[src][b][oofs][0];
        for (int i = t; i < 4096; i += 256) {
            int o = i >> 6, nl = i & 63;
            outb[(size_t)o * NTOK + n0 + nl] = __float2half_rn(stage[o * 64 + nl]);
        }
    }
}

// ---------------------------------------------------------------------------
// Flash cross-attention, fp16 mma (m16n8k16), O^T = V^T P^T, online max.
// grid (N/64, B, 2), block 256, 2 CTAs/SM. R9's block-wide copy + 4-sync
// skeleton, but all operands fp16 (half the mma instructions, LDS, bytes).
// ---------------------------------------------------------------------------
#define RSTR 36                               // u32 (half2) per smem row: 32 data + 4 pad
#define OFF_VT 0                              // 256 x 36 u32 = 36864 B
#define OFF_Q  36864                          // 64 x 36 u32  = 9216 B
#define OFF_K  46080                          // 64 x 36 u32
#define OFF_P  55296                          // 64 x 36 u32
#define OFF_MX 64512                          // rowmax[64] f32
#define OFF_RS 64768                          // rs[128] f32
#define OFF_SC 65280                          // scl[64] f32
#define OFF_MH 65536                          // mxh[128] f32
#define OFF_MC 66048                          // mxcur[64] f32
#define OFF_IV 66304                          // inv[64] f32
#define ATTN_SMEM 66560

__global__ __launch_bounds__(256, 2) void attn_kernel(
    const float* __restrict__ x1, const float* __restrict__ x2,
    const float* __restrict__ gamma_p, float* __restrict__ out)
{
    extern __shared__ char smem[];
    uint32_t* VT2 = (uint32_t*)(smem + OFF_VT);
    uint32_t* Q2  = (uint32_t*)(smem + OFF_Q);
    uint32_t* K2  = (uint32_t*)(smem + OFF_K);
    uint32_t* P2  = (uint32_t*)(smem + OFF_P);
    float* rowmax = (float*)(smem + OFF_MX);
    float* rs     = (float*)(smem + OFF_RS);
    float* scl    = (float*)(smem + OFF_SC);
    float* mxh    = (float*)(smem + OFF_MH);
    float* mxcur  = (float*)(smem + OFF_MC);
    float* inv    = (float*)(smem + OFF_IV);

    int qtile = blockIdx.x, b = blockIdx.y, dir = blockIdx.z;
    int srckv = dir ^ 1;
    const float* xq = dir ? x2 : x1;
    int n0 = qtile * 64;

    int t    = threadIdx.x;
    int warp = t >> 5, lane = t & 31;
    int g    = lane >> 2, tig = lane & 3;
    int wr   = warp >> 1, wc = warp & 1;
    int qb   = wr * 16;        // S-phase q-row base
    int cb   = warp * 32;      // PV-phase c-row base
    int r0   = qb + g, r1 = qb + g + 8;

    const float4* kg4 = (const float4*)&g_kh[srckv][b][0][0];
    const float4* vg4 = (const float4*)&g_vth[srckv][b][0][0];

    // ---- prologue: Q tile (fp16), state init ----
    {
        const float4* qg4 = (const float4*)&g_qh[dir][b][n0][0];
        #pragma unroll
        for (int j = 0; j < 2; j++) {
            int i = t + 256 * j;
            int row = i >> 3, ch = i & 7;
            *(float4*)(smem + OFF_Q + row * (RSTR * 4) + ch * 16) = qg4[i];
        }
    }
    if (t < 64) { rowmax[t] = -1e30f; mxcur[t] = -1e30f; }
    if (t < 128) rs[t] = 0.f;
    float oacc[16][4] = {};
    __syncthreads();

    for (int it = 0; it < NTOK / 64; it++) {
        // ---- copies: K tile (512 f4), V^T tile (2048 f4), block-wide coalesced
        {
            const float4* ks = kg4 + (size_t)it * 512;
            #pragma unroll
            for (int j = 0; j < 2; j++) {
                int i = t + 256 * j;
                int row = i >> 3, ch = i & 7;
                *(float4*)(smem + OFF_K + row * (RSTR * 4) + ch * 16) = ks[i];
            }
            #pragma unroll
            for (int j = 0; j < 8; j++) {
                int i = t + 256 * j;
                int c = i >> 3, ch = i & 7;
                *(float4*)(smem + OFF_VT + c * (RSTR * 4) + ch * 16) =
                    vg4[(size_t)c * 512 + it * 8 + ch];
            }
        }
        __syncthreads();   // A: tiles visible

        // ---- S = Q K^T (fp16, m16n8k16): warp = 16 q-rows x 32 m-cols ----
        float sf[4][4] = {};
        #pragma unroll
        for (int kk = 0; kk < 4; kk++) {
            int k0 = kk * 8;
            uint32_t a0 = Q2[r0 * RSTR + k0 + tig];
            uint32_t a1 = Q2[r1 * RSTR + k0 + tig];
            uint32_t a2 = Q2[r0 * RSTR + k0 + tig + 4];
            uint32_t a3 = Q2[r1 * RSTR + k0 + tig + 4];
            #pragma unroll
            for (int nb = 0; nb < 4; nb++) {
                int m = wc * 32 + nb * 8;
                uint32_t b0 = K2[(m + g) * RSTR + k0 + tig];
                uint32_t b1 = K2[(m + g) * RSTR + k0 + tig + 4];
                mma_fp16(sf[nb], a0, a1, a2, a3, b0, b1);
            }
        }
        // local (half-row) max
        {
            float lm0 = -1e30f, lm1 = -1e30f;
            #pragma unroll
            for (int nb = 0; nb < 4; nb++) {
                lm0 = fmaxf(lm0, fmaxf(sf[nb][0], sf[nb][1]));
                lm1 = fmaxf(lm1, fmaxf(sf[nb][2], sf[nb][3]));
            }
            lm0 = fmaxf(lm0, __shfl_xor_sync(0xffffffffu, lm0, 1));
            lm0 = fmaxf(lm0, __shfl_xor_sync(0xffffffffu, lm0, 2));
            lm1 = fmaxf(lm1, __shfl_xor_sync(0xffffffffu, lm1, 1));
            lm1 = fmaxf(lm1, __shfl_xor_sync(0xffffffffu, lm1, 2));
            if (tig == 0) { mxh[wc * 64 + r0] = lm0; mxh[wc * 64 + r1] = lm1; }
        }
        __syncthreads();   // M: cross-half maxima visible

        // ---- online softmax: P = exp(s - newmax) -> fp16 ----
        {
            float om0 = rowmax[r0], om1 = rowmax[r1];
            float nm0 = fmaxf(om0, fmaxf(mxh[r0], mxh[64 + r0]));
            float nm1 = fmaxf(om1, fmaxf(mxh[r1], mxh[64 + r1]));
            float ps0 = 0.f, ps1 = 0.f;
            #pragma unroll
            for (int nb = 0; nb < 4; nb++) {
                float p0 = fexp(sf[nb][0] - nm0);
                float p1 = fexp(sf[nb][1] - nm0);
                float p2 = fexp(sf[nb][2] - nm1);
                float p3 = fexp(sf[nb][3] - nm1);
                ps0 += p0 + p1;
                ps1 += p2 + p3;
                int col2 = wc * 16 + nb * 4 + tig;
                P2[r0 * RSTR + col2] = h2_of(p0, p1);
                P2[r1 * RSTR + col2] = h2_of(p2, p3);
            }
            ps0 += __shfl_xor_sync(0xffffffffu, ps0, 1);
            ps0 += __shfl_xor_sync(0xffffffffu, ps0, 2);
            ps1 += __shfl_xor_sync(0xffffffffu, ps1, 1);
            ps1 += __shfl_xor_sync(0xffffffffu, ps1, 2);
            if (tig == 0) {
                rs[wc * 64 + r0] = rs[wc * 64 + r0] * fexp(om0 - nm0) + ps0;
                rs[wc * 64 + r1] = rs[wc * 64 + r1] * fexp(om1 - nm1) + ps1;
                if (wc == 0) {
                    scl[r0] = fexp(om0 - nm0);
                    scl[r1] = fexp(om1 - nm1);
                    mxcur[r0] = nm0;
                    mxcur[r1] = nm1;
                }
            }
        }
        __syncthreads();   // P: P + scl visible

        // race-free rowmax publish (reads happen after next M-barrier)
        if (t < 64) rowmax[t] = mxcur[t];

        // ---- O^T = O^T*scl + V^T P^T (fp16): warp = 32 c-rows x 64 q-cols ----
        #pragma unroll
        for (int nb = 0; nb < 8; nb++) {
            int q = nb * 8 + tig * 2;
            float2 sc = *(float2*)&scl[q];
            oacc[nb][0] *= sc.x; oacc[nb][1] *= sc.y;
            oacc[nb][2] *= sc.x; oacc[nb][3] *= sc.y;
            oacc[8 + nb][0] *= sc.x; oacc[8 + nb][1] *= sc.y;
            oacc[8 + nb][2] *= sc.x; oacc[8 + nb][3] *= sc.y;
        }
        #pragma unroll
        for (int kk = 0; kk < 4; kk++) {
            int k0 = kk * 8;
            uint32_t a00 = VT2[(cb + g)      * RSTR + k0 + tig];
            uint32_t a01 = VT2[(cb + g + 8)  * RSTR + k0 + tig];
            uint32_t a02 = VT2[(cb + g)      * RSTR + k0 + tig + 4];
            uint32_t a03 = VT2[(cb + g + 8)  * RSTR + k0 + tig + 4];
            uint32_t a10 = VT2[(cb + g + 16) * RSTR + k0 + tig];
            uint32_t a11 = VT2[(cb + g + 24) * RSTR + k0 + tig];
            uint32_t a12 = VT2[(cb + g + 16) * RSTR + k0 + tig + 4];
            uint32_t a13 = VT2[(cb + g + 24) * RSTR + k0 + tig + 4];
            #pragma unroll
            for (int nb = 0; nb < 8; nb++) {
                uint32_t b0 = P2[(nb * 8 + g) * RSTR + k0 + tig];
                uint32_t b1 = P2[(nb * 8 + g) * RSTR + k0 + tig + 4];
                mma_fp16(oacc[nb],     a00, a01, a02, a03, b0, b1);
                mma_fp16(oacc[8 + nb], a10, a11, a12, a13, b0, b1);
            }
        }
        __syncthreads();   // E: PV reads done; buffers reusable
    }

    // ---- epilogue: normalize + residual, direct float2 stores ----
    if (t < 64) inv[t] = 1.f / (rs[t] + rs[64 + t]);
    __syncthreads();

    float gm = gamma_p[0];
    size_t obase = ((size_t)(dir * BATCH + b)) * CDIM * NTOK;
    const float* xb = xq + (size_t)b * CDIM * NTOK;

    #pragma unroll
    for (int nb = 0; nb < 8; nb++) {
        int q = nb * 8 + tig * 2;
        float2 iv = *(float2*)&inv[q];
        int crows[4] = { cb + g, cb + g + 8, cb + g + 16, cb + g + 24 };
        float ox[4][2] = {
            { oacc[nb][0],     oacc[nb][1]     },
            { oacc[nb][2],     oacc[nb][3]     },
            { oacc[8 + nb][0], oacc[8 + nb][1] },
            { oacc[8 + nb][2], oacc[8 + nb][3] },
        };
        #pragma unroll
        for (int rr = 0; rr < 4; rr++) {
            size_t idx = (size_t)crows[rr] * NTOK + n0 + q;
            float2 xv = *(const float2*)&xb[idx];
            float2 ov;
            ov.x = xv.x + gm * iv.x * ox[rr][0];
            ov.y = xv.y + gm * iv.y * ox[rr][1];
            *(float2*)&out[obase + idx] = ov;
        }
    }
}

extern "C" void kernel_launch(void* const* d_in, const int* in_sizes, int n_in,
                              void* d_out, int out_size)
{
    const float* x1    = (const float*)d_in[0];
    const float* x2    = (const float*)d_in[1];
    const float* Wq    = (const float*)d_in[2];
    const float* bq    = (const float*)d_in[3];
    const float* Wk    = (const float*)d_in[4];
    const float* bk    = (const float*)d_in[5];
    const float* Wv    = (const float*)d_in[6];
    const float* bv    = (const float*)d_in[7];
    const float* gamma = (const float*)d_in[8];
    float* out = (float*)d_out;
    (void)in_sizes; (void)n_in; (void)out_size;

    cudaFuncSetAttribute(attn_kernel, cudaFuncAttributeMaxDynamicSharedMemorySize,
                         ATTN_SMEM);

    proj_kernel<<<dim3(NTOK / 64, 6, 2 * BATCH), 256>>>(x1, x2, Wq, bq, Wk, bk, Wv, bv);
    attn_kernel<<<dim3(NTOK / 64, BATCH, 2), 256, ATTN_SMEM>>>(x1, x2, gamma, out);
}

// round 13
// speedup vs baseline: 3.2152x; 1.0101x over previous
#include <cuda_runtime.h>
#include <cuda_fp16.h>
#include <cstdint>

#define NTOK  4096
#define CDIM  256
#define HIDD  64
#define BATCH 4

// Projection scratch, fp16: q,k: [src][b][n][64]; v TRANSPOSED: [src][b][c][m]
__device__ __half g_qh[2][BATCH][NTOK][HIDD];
__device__ __half g_kh[2][BATCH][NTOK][HIDD];
__device__ __half g_vth[2][BATCH][CDIM][NTOK];

// ---------------------------------------------------------------------------
// helpers
// ---------------------------------------------------------------------------
__device__ __forceinline__ float to_tf32(float x) {
    uint32_t u;
    asm("cvt.rna.tf32.f32 %0, %1;" : "=r"(u) : "f"(x));
    return __uint_as_float(u);
}

__device__ __forceinline__ void mma_tf32(float c[4],
                                         uint32_t a0, uint32_t a1, uint32_t a2, uint32_t a3,
                                         uint32_t b0, uint32_t b1) {
    asm volatile(
        "mma.sync.aligned.m16n8k8.row.col.f32.tf32.tf32.f32 "
        "{%0,%1,%2,%3}, {%4,%5,%6,%7}, {%8,%9}, {%0,%1,%2,%3};\n"
        : "+f"(c[0]), "+f"(c[1]), "+f"(c[2]), "+f"(c[3])
        : "r"(a0), "r"(a1), "r"(a2), "r"(a3), "r"(b0), "r"(b1));
}

__device__ __forceinline__ void mma_fp16(float c[4],
                                         uint32_t a0, uint32_t a1, uint32_t a2, uint32_t a3,
                                         uint32_t b0, uint32_t b1) {
    asm volatile(
        "mma.sync.aligned.m16n8k16.row.col.f32.f16.f16.f32 "
        "{%0,%1,%2,%3}, {%4,%5,%6,%7}, {%8,%9}, {%0,%1,%2,%3};\n"
        : "+f"(c[0]), "+f"(c[1]), "+f"(c[2]), "+f"(c[3])
        : "r"(a0), "r"(a1), "r"(a2), "r"(a3), "r"(b0), "r"(b1));
}

// fast exp on the FMA pipe
__device__ __forceinline__ float fexp(float x) {
    float t = x * 1.4426950408889634f;
    t = fmaxf(t, -126.0f);
    float fi = t + 12582912.0f;
    int   ii = __float_as_int(fi) - 0x4B400000;
    float fr = t - (fi - 12582912.0f);
    float u  = fr * 0.6931471805599453f;
    float p  = 8.3333337e-3f;
    p = fmaf(p, u, 4.1666668e-2f);
    p = fmaf(p, u, 0.16666667f);
    p = fmaf(p, u, 0.5f);
    p = fmaf(p, u, 1.0f);
    p = fmaf(p, u, 1.0f);
    return __int_as_float(__float_as_int(p) + (ii << 23));
}

__device__ __forceinline__ uint32_t h2_of(float a, float b) {
    __half2 h = __floats2half2_rn(a, b);
    return *(uint32_t*)&h;
}

__device__ __forceinline__ void cp16(uint32_t dst_smem, const void* src_gmem) {
    asm volatile("cp.async.cg.shared.global [%0], [%1], 16;"
                 :: "r"(dst_smem), "l"(src_gmem) : "memory");
}

// ---------------------------------------------------------------------------
// Projection via tf32 mma (unchanged, passing) — fp16 epilogue.
// ---------------------------------------------------------------------------
__global__ __launch_bounds__(256) void proj_kernel(
    const float* __restrict__ x1, const float* __restrict__ x2,
    const float* __restrict__ Wq, const float* __restrict__ bq,
    const float* __restrict__ Wk, const float* __restrict__ bk,
    const float* __restrict__ Wv, const float* __restrict__ bv)
{
    int ntile = blockIdx.x;
    int otile = blockIdx.y;
    int src   = blockIdx.z >> 2;
    int b     = blockIdx.z & 3;
    const float* x = src ? x2 : x1;

    const float* W; const float* bias; int oofs;
    if (otile == 0)      { W = Wq; bias = bq; oofs = 0; }
    else if (otile == 1) { W = Wk; bias = bk; oofs = 0; }
    else                 { W = Wv; bias = bv; oofs = (otile - 2) * 64; }

    __shared__ float Ws[64][68];
    __shared__ float Xs[64][72];

    int t    = threadIdx.x;
    int warp = t >> 5, lane = t & 31;
    int g    = lane >> 2, tig = lane & 3;
    int wr   = warp >> 1, wc = warp & 1;
    int n0   = ntile * 64;

    float acc[4][4] = {};
    const float4* W4 = (const float4*)W;

    for (int cc = 0; cc < CDIM; cc += 64) {
        for (int i = t; i < 1024; i += 256) {
            int r = i >> 4, kq = i & 15;
            float4 w = W4[(size_t)(oofs + r) * 64 + (cc >> 2) + kq];
            Ws[r][kq * 4 + 0] = to_tf32(w.x);
            Ws[r][kq * 4 + 1] = to_tf32(w.y);
            Ws[r][kq * 4 + 2] = to_tf32(w.z);
            Ws[r][kq * 4 + 3] = to_tf32(w.w);
        }
        const float4* X4 = (const float4*)x;
        for (int i = t; i < 1024; i += 256) {
            int r = i >> 4, cq = i & 15;
            float4 v = X4[(size_t)(b * CDIM + cc + r) * (NTOK / 4) + (n0 >> 2) + cq];
            Xs[r][cq * 4 + 0] = to_tf32(v.x);
            Xs[r][cq * 4 + 1] = to_tf32(v.y);
            Xs[r][cq * 4 + 2] = to_tf32(v.z);
            Xs[r][cq * 4 + 3] = to_tf32(v.w);
        }
        __syncthreads();
        int ob = wr * 16;
        #pragma unroll
        for (int kk = 0; kk < 8; kk++) {
            int k0 = kk * 8;
            uint32_t a0 = __float_as_uint(Ws[ob + g][k0 + tig]);
            uint32_t a1 = __float_as_uint(Ws[ob + g + 8][k0 + tig]);
            uint32_t a2 = __float_as_uint(Ws[ob + g][k0 + tig + 4]);
            uint32_t a3 = __float_as_uint(Ws[ob + g + 8][k0 + tig + 4]);
            #pragma unroll
            for (int j = 0; j < 4; j++) {
                int nb = wc * 32 + j * 8;
                uint32_t b0 = __float_as_uint(Xs[k0 + tig][nb + g]);
                uint32_t b1 = __float_as_uint(Xs[k0 + tig + 4][nb + g]);
                mma_tf32(acc[j], a0, a1, a2, a3, b0, b1);
            }
        }
        __syncthreads();
    }

    float* stage = &Ws[0][0];
    int o0 = wr * 16 + g, o1 = o0 + 8;
    float bz0 = bias[oofs + o0], bz1 = bias[oofs + o1];

    if (otile < 2) {
        #pragma unroll
        for (int j = 0; j < 4; j++) {
            int nl = wc * 32 + j * 8 + tig * 2;
            stage[(nl)     * 64 + o0] = acc[j][0] + bz0;
            stage[(nl + 1) * 64 + o0] = acc[j][1] + bz0;
            stage[(nl)     * 64 + o1] = acc[j][2] + bz1;
            stage[(nl + 1) * 64 + o1] = acc[j][3] + bz1;
        }
        __syncthreads();
        __half* outb = (otile == 0) ? &g_qh[src][b][0][0] : &g_kh[src][b][0][0];
        for (int i = t; i < 4096; i += 256) {
            int nl = i >> 6, o = i & 63;
            outb[(size_t)(n0 + nl) * 64 + o] = __float2half_rn(stage[nl * 64 + o]);
        }
    } else {
        #pragma unroll
        for (int j = 0; j < 4; j++) {
            int nl = wc * 32 + j * 8 + tig * 2;
            stage[o0 * 64 + nl]     = acc[j][0] + bz0;
            stage[o0 * 64 + nl + 1] = acc[j][1] + bz0;
            stage[o1 * 64 + nl]     = acc[j][2] + bz1;
            stage[o1 * 64 + nl + 1] = acc[j][3] + bz1;
        }
        __syncthreads();
        __half* outb = &g_vth[src][b][oofs][0];
        for (int i = t; i < 4096; i += 256) {
            int o = i >> 6, nl = i & 63;
            outb[(size_t)o * NTOK + n0 + nl] = __float2half_rn(stage[o * 64 + nl]);
        }
    }
}

// ---------------------------------------------------------------------------
// Flash cross-attention, fp16 mma, cp.async double-buffered K/V prefetch.
// grid (N/64, B, 2), block 256, 2 CTAs/SM. 3 barriers/iter:
//   [wait cp.async][barA] prefetch(i+1) S_i [barM] softmax->P [barP] (rescale?) PV_i
// ---------------------------------------------------------------------------
#define RSTR 36                               // u32 (half2) per smem row
#define VT_BYTES 36864                        // 256 x 36 x 4
#define K_BYTES  9216                         // 64 x 36 x 4
#define OFF_VT0 0
#define OFF_VT1 36864
#define OFF_K0  73728
#define OFF_K1  82944
#define OFF_Q   92160
#define OFF_P   101376
#define OFF_MX  110592
#define OFF_RS  110848
#define OFF_SC  111360
#define OFF_MH  111616
#define OFF_MC  112128
#define OFF_IV  112384
#define OFF_FL  112640
#define ATTN_SMEM 112768

__global__ __launch_bounds__(256, 2) void attn_kernel(
    const float* __restrict__ x1, const float* __restrict__ x2,
    const float* __restrict__ gamma_p, float* __restrict__ out)
{
    extern __shared__ char smem[];
    uint32_t sb = (uint32_t)__cvta_generic_to_shared(smem);

    uint32_t* Q2  = (uint32_t*)(smem + OFF_Q);
    uint32_t* P2  = (uint32_t*)(smem + OFF_P);
    float* rowmax = (float*)(smem + OFF_MX);
    float* rs     = (float*)(smem + OFF_RS);
    float* scl    = (float*)(smem + OFF_SC);
    float* mxh    = (float*)(smem + OFF_MH);
    float* mxcur  = (float*)(smem + OFF_MC);
    float* inv    = (float*)(smem + OFF_IV);
    int*   flag   = (int*)(smem + OFF_FL);

    int qtile = blockIdx.x, b = blockIdx.y, dir = blockIdx.z;
    int srckv = dir ^ 1;
    const float* xq = dir ? x2 : x1;
    int n0 = qtile * 64;

    int t    = threadIdx.x;
    int warp = t >> 5, lane = t & 31;
    int g    = lane >> 2, tig = lane & 3;
    int wr   = warp >> 1, wc = warp & 1;
    int qb   = wr * 16;
    int cb   = warp * 32;
    int r0   = qb + g, r1 = qb + g + 8;

    const float4* kg4 = (const float4*)&g_kh[srckv][b][0][0];
    const float4* vg4 = (const float4*)&g_vth[srckv][b][0][0];

    // ---- prologue: Q tile; prefetch tile 0 ----
    {
        const float4* qg4 = (const float4*)&g_qh[dir][b][n0][0];
        #pragma unroll
        for (int j = 0; j < 2; j++) {
            int i = t + 256 * j;
            int row = i >> 3, ch = i & 7;
            *(float4*)(smem + OFF_Q + row * (RSTR * 4) + ch * 16) = qg4[i];
        }
    }
    {
        #pragma unroll
        for (int j = 0; j < 2; j++) {
            int i = t + 256 * j;
            int row = i >> 3, ch = i & 7;
            cp16(sb + OFF_K0 + row * (RSTR * 4) + ch * 16, kg4 + i);
        }
        #pragma unroll
        for (int j = 0; j < 8; j++) {
            int i = t + 256 * j;
            int c = i >> 3, ch = i & 7;
            cp16(sb + OFF_VT0 + c * (RSTR * 4) + ch * 16, vg4 + (size_t)c * 512 + ch);
        }
        asm volatile("cp.async.commit_group;" ::: "memory");
    }
    if (t < 64) { rowmax[t] = -1e30f; mxcur[t] = -1e30f; }
    if (t < 128) rs[t] = 0.f;
    float oacc[16][4] = {};

    for (int it = 0; it < NTOK / 64; it++) {
        uint32_t* K2  = (uint32_t*)(smem + OFF_K0  + (it & 1) * K_BYTES);
        uint32_t* VT2 = (uint32_t*)(smem + OFF_VT0 + (it & 1) * VT_BYTES);

        asm volatile("cp.async.wait_group 0;" ::: "memory");
        __syncthreads();   // A: tile it visible everywhere; prev iter fully done

        if (t == 0) *flag = 0;

        // ---- prefetch tile it+1 into the other buffer ----
        if (it < NTOK / 64 - 1) {
            int itn = it + 1;
            uint32_t kb = sb + OFF_K0  + (itn & 1) * K_BYTES;
            uint32_t vb = sb + OFF_VT0 + (itn & 1) * VT_BYTES;
            const float4* ks = kg4 + (size_t)itn * 512;
            #pragma unroll
            for (int j = 0; j < 2; j++) {
                int i = t + 256 * j;
                int row = i >> 3, ch = i & 7;
                cp16(kb + row * (RSTR * 4) + ch * 16, ks + i);
            }
            #pragma unroll
            for (int j = 0; j < 8; j++) {
                int i = t + 256 * j;
                int c = i >> 3, ch = i & 7;
                cp16(vb + c * (RSTR * 4) + ch * 16,
                     vg4 + (size_t)c * 512 + itn * 8 + ch);
            }
            asm volatile("cp.async.commit_group;" ::: "memory");
        }

        // ---- S = Q K^T (fp16): warp = 16 q-rows x 32 m-cols ----
        float sf[4][4] = {};
        #pragma unroll
        for (int kk = 0; kk < 4; kk++) {
            int k0 = kk * 8;
            uint32_t a0 = Q2[r0 * RSTR + k0 + tig];
            uint32_t a1 = Q2[r1 * RSTR + k0 + tig];
            uint32_t a2 = Q2[r0 * RSTR + k0 + tig + 4];
            uint32_t a3 = Q2[r1 * RSTR + k0 + tig + 4];
            #pragma unroll
            for (int nb = 0; nb < 4; nb++) {
                int m = wc * 32 + nb * 8;
                uint32_t b0 = K2[(m + g) * RSTR + k0 + tig];
                uint32_t b1 = K2[(m + g) * RSTR + k0 + tig + 4];
                mma_fp16(sf[nb], a0, a1, a2, a3, b0, b1);
            }
        }
        // local (half-row) max
        {
            float lm0 = -1e30f, lm1 = -1e30f;
            #pragma unroll
            for (int nb = 0; nb < 4; nb++) {
                lm0 = fmaxf(lm0, fmaxf(sf[nb][0], sf[nb][1]));
                lm1 = fmaxf(lm1, fmaxf(sf[nb][2], sf[nb][3]));
            }
            lm0 = fmaxf(lm0, __shfl_xor_sync(0xffffffffu, lm0, 1));
            lm0 = fmaxf(lm0, __shfl_xor_sync(0xffffffffu, lm0, 2));
            lm1 = fmaxf(lm1, __shfl_xor_sync(0xffffffffu, lm1, 1));
            lm1 = fmaxf(lm1, __shfl_xor_sync(0xffffffffu, lm1, 2));
            if (tig == 0) { mxh[wc * 64 + r0] = lm0; mxh[wc * 64 + r1] = lm1; }
        }
        __syncthreads();   // M: cross-half maxima + flag reset visible

        // ---- online softmax: P = exp(s - newmax) -> fp16 ----
        {
            float om0 = rowmax[r0], om1 = rowmax[r1];
            float nm0 = fmaxf(om0, fmaxf(mxh[r0], mxh[64 + r0]));
            float nm1 = fmaxf(om1, fmaxf(mxh[r1], mxh[64 + r1]));
            float ps0 = 0.f, ps1 = 0.f;
            #pragma unroll
            for (int nb = 0; nb < 4; nb++) {
                float p0 = fexp(sf[nb][0] - nm0);
                float p1 = fexp(sf[nb][1] - nm0);
                float p2 = fexp(sf[nb][2] - nm1);
                float p3 = fexp(sf[nb][3] - nm1);
                ps0 += p0 + p1;
                ps1 += p2 + p3;
                int col2 = wc * 16 + nb * 4 + tig;
                P2[r0 * RSTR + col2] = h2_of(p0, p1);
                P2[r1 * RSTR + col2] = h2_of(p2, p3);
            }
            ps0 += __shfl_xor_sync(0xffffffffu, ps0, 1);
            ps0 += __shfl_xor_sync(0xffffffffu, ps0, 2);
            ps1 += __shfl_xor_sync(0xffffffffu, ps1, 1);
            ps1 += __shfl_xor_sync(0xffffffffu, ps1, 2);
            if (tig == 0) {
                if (nm0 > om0 || nm1 > om1) *flag = 1;
                rs[wc * 64 + r0] = rs[wc * 64 + r0] * fexp(om0 - nm0) + ps0;
                rs[wc * 64 + r1] = rs[wc * 64 + r1] * fexp(om1 - nm1) + ps1;
                if (wc == 0) {
                    scl[r0] = fexp(om0 - nm0);
                    scl[r1] = fexp(om1 - nm1);
                    mxcur[r0] = nm0;
                    mxcur[r1] = nm1;
                }
            }
        }
        __syncthreads();   // P: P + scl + flag visible

        // race-free rowmax publish (read next iter after barrier M)
        if (t < 64) rowmax[t] = mxcur[t];

        // ---- conditional O rescale (uniform branch; rare after warmup) ----
        if (*flag) {
            #pragma unroll
            for (int nb = 0; nb < 8; nb++) {
                int q = nb * 8 + tig * 2;
                float2 sc = *(float2*)&scl[q];
                oacc[nb][0] *= sc.x; oacc[nb][1] *= sc.y;
                oacc[nb][2] *= sc.x; oacc[nb][3] *= sc.y;
                oacc[8 + nb][0] *= sc.x; oacc[8 + nb][1] *= sc.y;
                oacc[8 + nb][2] *= sc.x; oacc[8 + nb][3] *= sc.y;
            }
        }

        // ---- O^T += V^T P^T (fp16): warp = 32 c-rows x 64 q-cols ----
        #pragma unroll
        for (int kk = 0; kk < 4; kk++) {
            int k0 = kk * 8;
            uint32_t a00 = VT2[(cb + g)      * RSTR + k0 + tig];
            uint32_t a01 = VT2[(cb + g + 8)  * RSTR + k0 + tig];
            uint32_t a02 = VT2[(cb + g)      * RSTR + k0 + tig + 4];
            uint32_t a03 = VT2[(cb + g + 8)  * RSTR + k0 + tig + 4];
            uint32_t a10 = VT2[(cb + g + 16) * RSTR + k0 + tig];
            uint32_t a11 = VT2[(cb + g + 24) * RSTR + k0 + tig];
            uint32_t a12 = VT2[(cb + g + 16) * RSTR + k0 + tig + 4];
            uint32_t a13 = VT2[(cb + g + 24) * RSTR + k0 + tig + 4];
            #pragma unroll
            for (int nb = 0; nb < 8; nb++) {
                uint32_t b0 = P2[(nb * 8 + g) * RSTR + k0 + tig];
                uint32_t b1 = P2[(nb * 8 + g) * RSTR + k0 + tig + 4];
                mma_fp16(oacc[nb],     a00, a01, a02, a03, b0, b1);
                mma_fp16(oacc[8 + nb], a10, a11, a12, a13, b0, b1);
            }
        }
        // no trailing barrier: next iter's barA orders everything
    }

    // ---- epilogue: normalize + residual, direct float2 stores ----
    __syncthreads();
    if (t < 64) inv[t] = 1.f / (rs[t] + rs[64 + t]);
    __syncthreads();

    float gm = gamma_p[0];
    size_t obase = ((size_t)(dir * BATCH + b)) * CDIM * NTOK;
    const float* xb = xq + (size_t)b * CDIM * NTOK;

    #pragma unroll
    for (int nb = 0; nb < 8; nb++) {
        int q = nb * 8 + tig * 2;
        float2 iv = *(float2*)&inv[q];
        int crows[4] = { cb + g, cb + g + 8, cb + g + 16, cb + g + 24 };
        float ox[4][2] = {
            { oacc[nb][0],     oacc[nb][1]     },
            { oacc[nb][2],     oacc[nb][3]     },
            { oacc[8 + nb][0], oacc[8 + nb][1] },
            { oacc[8 + nb][2], oacc[8 + nb][3] },
        };
        #pragma unroll
        for (int rr = 0; rr < 4; rr++) {
            size_t idx = (size_t)crows[rr] * NTOK + n0 + q;
            float2 xv = *(const float2*)&xb[idx];
            float2 ov;
            ov.x = xv.x + gm * iv.x * ox[rr][0];
            ov.y = xv.y + gm * iv.y * ox[rr][1];
            *(float2*)&out[obase + idx] = ov;
        }
    }
}

extern "C" void kernel_launch(void* const* d_in, const int* in_sizes, int n_in,
                              void* d_out, int out_size)
{
    const float* x1    = (const float*)d_in[0];
    const float* x2    = (const float*)d_in[1];
    const float* Wq    = (const float*)d_in[2];
    const float* bq    = (const float*)d_in[3];
    const float* Wk    = (const float*)d_in[4];
    const float* bk    = (const float*)d_in[5];
    const float* Wv    = (const float*)d_in[6];
    const float* bv    = (const float*)d_in[7];
    const float* gamma = (const float*)d_in[8];
    float* out = (float*)d_out;
    (void)in_sizes; (void)n_in; (void)out_size;

    cudaFuncSetAttribute(attn_kernel, cudaFuncAttributeMaxDynamicSharedMemorySize,
                         ATTN_SMEM);

    proj_kernel<<<dim3(NTOK / 64, 6, 2 * BATCH), 256>>>(x1, x2, Wq, bq, Wk, bk, Wv, bv);
    attn_kernel<<<dim3(NTOK / 64, BATCH, 2), 256, ATTN_SMEM>>>(x1, x2, gamma, out);
}

// round 14
// speedup vs baseline: 3.4548x; 1.0745x over previous
#include <cuda_runtime.h>
#include <cuda_fp16.h>
#include <cstdint>

#define NTOK  4096
#define CDIM  256
#define HIDD  64
#define BATCH 4

// Projection scratch, fp16: q,k: [src][b][n][64]; v TRANSPOSED: [src][b][c][m]
// NOTE: q is pre-scaled by log2(e) so S = Q'K^T is in the log2 domain.
__device__ __half g_qh[2][BATCH][NTOK][HIDD];
__device__ __half g_kh[2][BATCH][NTOK][HIDD];
__device__ __half g_vth[2][BATCH][CDIM][NTOK];

// ---------------------------------------------------------------------------
// helpers
// ---------------------------------------------------------------------------
__device__ __forceinline__ float to_tf32(float x) {
    uint32_t u;
    asm("cvt.rna.tf32.f32 %0, %1;" : "=r"(u) : "f"(x));
    return __uint_as_float(u);
}

__device__ __forceinline__ void mma_tf32(float c[4],
                                         uint32_t a0, uint32_t a1, uint32_t a2, uint32_t a3,
                                         uint32_t b0, uint32_t b1) {
    asm volatile(
        "mma.sync.aligned.m16n8k8.row.col.f32.tf32.tf32.f32 "
        "{%0,%1,%2,%3}, {%4,%5,%6,%7}, {%8,%9}, {%0,%1,%2,%3};\n"
        : "+f"(c[0]), "+f"(c[1]), "+f"(c[2]), "+f"(c[3])
        : "r"(a0), "r"(a1), "r"(a2), "r"(a3), "r"(b0), "r"(b1));
}

__device__ __forceinline__ void mma_fp16(float c[4],
                                         uint32_t a0, uint32_t a1, uint32_t a2, uint32_t a3,
                                         uint32_t b0, uint32_t b1) {
    asm volatile(
        "mma.sync.aligned.m16n8k16.row.col.f32.f16.f16.f32 "
        "{%0,%1,%2,%3}, {%4,%5,%6,%7}, {%8,%9}, {%0,%1,%2,%3};\n"
        : "+f"(c[0]), "+f"(c[1]), "+f"(c[2]), "+f"(c[3])
        : "r"(a0), "r"(a1), "r"(a2), "r"(a3), "r"(b0), "r"(b1));
}

// exp2 on the MUFU pipe (input already in log2 domain)
__device__ __forceinline__ float ex2f(float x) {
    float r;
    asm("ex2.approx.f32 %0, %1;" : "=f"(r) : "f"(x));
    return r;
}

__device__ __forceinline__ uint32_t h2_of(float a, float b) {
    __half2 h = __floats2half2_rn(a, b);
    return *(uint32_t*)&h;
}

__device__ __forceinline__ void cp16(uint32_t dst_smem, const void* src_gmem) {
    asm volatile("cp.async.cg.shared.global [%0], [%1], 16;"
                 :: "r"(dst_smem), "l"(src_gmem) : "memory");
}

#define LOG2E 1.4426950408889634f

// ---------------------------------------------------------------------------
// Projection via tf32 mma — fp16 epilogue; Q additionally scaled by log2e.
// ---------------------------------------------------------------------------
__global__ __launch_bounds__(256) void proj_kernel(
    const float* __restrict__ x1, const float* __restrict__ x2,
    const float* __restrict__ Wq, const float* __restrict__ bq,
    const float* __restrict__ Wk, const float* __restrict__ bk,
    const float* __restrict__ Wv, const float* __restrict__ bv)
{
    int ntile = blockIdx.x;
    int otile = blockIdx.y;
    int src   = blockIdx.z >> 2;
    int b     = blockIdx.z & 3;
    const float* x = src ? x2 : x1;

    const float* W; const float* bias; int oofs;
    if (otile == 0)      { W = Wq; bias = bq; oofs = 0; }
    else if (otile == 1) { W = Wk; bias = bk; oofs = 0; }
    else                 { W = Wv; bias = bv; oofs = (otile - 2) * 64; }

    __shared__ float Ws[64][68];
    __shared__ float Xs[64][72];

    int t    = threadIdx.x;
    int warp = t >> 5, lane = t & 31;
    int g    = lane >> 2, tig = lane & 3;
    int wr   = warp >> 1, wc = warp & 1;
    int n0   = ntile * 64;

    float acc[4][4] = {};
    const float4* W4 = (const float4*)W;

    for (int cc = 0; cc < CDIM; cc += 64) {
        for (int i = t; i < 1024; i += 256) {
            int r = i >> 4, kq = i & 15;
            float4 w = W4[(size_t)(oofs + r) * 64 + (cc >> 2) + kq];
            Ws[r][kq * 4 + 0] = to_tf32(w.x);
            Ws[r][kq * 4 + 1] = to_tf32(w.y);
            Ws[r][kq * 4 + 2] = to_tf32(w.z);
            Ws[r][kq * 4 + 3] = to_tf32(w.w);
        }
        const float4* X4 = (const float4*)x;
        for (int i = t; i < 1024; i += 256) {
            int r = i >> 4, cq = i & 15;
            float4 v = X4[(size_t)(b * CDIM + cc + r) * (NTOK / 4) + (n0 >> 2) + cq];
            Xs[r][cq * 4 + 0] = to_tf32(v.x);
            Xs[r][cq * 4 + 1] = to_tf32(v.y);
            Xs[r][cq * 4 + 2] = to_tf32(v.z);
            Xs[r][cq * 4 + 3] = to_tf32(v.w);
        }
        __syncthreads();
        int ob = wr * 16;
        #pragma unroll
        for (int kk = 0; kk < 8; kk++) {
            int k0 = kk * 8;
            uint32_t a0 = __float_as_uint(Ws[ob + g][k0 + tig]);
            uint32_t a1 = __float_as_uint(Ws[ob + g + 8][k0 + tig]);
            uint32_t a2 = __float_as_uint(Ws[ob + g][k0 + tig + 4]);
            uint32_t a3 = __float_as_uint(Ws[ob + g + 8][k0 + tig + 4]);
            #pragma unroll
            for (int j = 0; j < 4; j++) {
                int nb = wc * 32 + j * 8;
                uint32_t b0 = __float_as_uint(Xs[k0 + tig][nb + g]);
                uint32_t b1 = __float_as_uint(Xs[k0 + tig + 4][nb + g]);
                mma_tf32(acc[j], a0, a1, a2, a3, b0, b1);
            }
        }
        __syncthreads();
    }

    float* stage = &Ws[0][0];
    int o0 = wr * 16 + g, o1 = o0 + 8;
    float bz0 = bias[oofs + o0], bz1 = bias[oofs + o1];

    if (otile < 2) {
        float s = (otile == 0) ? LOG2E : 1.0f;   // Q carries the log2e factor
        #pragma unroll
        for (int j = 0; j < 4; j++) {
            int nl = wc * 32 + j * 8 + tig * 2;
            stage[(nl)     * 64 + o0] = (acc[j][0] + bz0) * s;
            stage[(nl + 1) * 64 + o0] = (acc[j][1] + bz0) * s;
            stage[(nl)     * 64 + o1] = (acc[j][2] + bz1) * s;
            stage[(nl + 1) * 64 + o1] = (acc[j][3] + bz1) * s;
        }
        __syncthreads();
        __half* outb = (otile == 0) ? &g_qh[src][b][0][0] : &g_kh[src][b][0][0];
        for (int i = t; i < 4096; i += 256) {
            int nl = i >> 6, o = i & 63;
            outb[(size_t)(n0 + nl) * 64 + o] = __float2half_rn(stage[nl * 64 + o]);
        }
    } else {
        #pragma unroll
        for (int j = 0; j < 4; j++) {
            int nl = wc * 32 + j * 8 + tig * 2;
            stage[o0 * 64 + nl]     = acc[j][0] + bz0;
            stage[o0 * 64 + nl + 1] = acc[j][1] + bz0;
            stage[o1 * 64 + nl]     = acc[j][2] + bz1;
            stage[o1 * 64 + nl + 1] = acc[j][3] + bz1;
        }
        __syncthreads();
        __half* outb = &g_vth[src][b][oofs][0];
        for (int i = t; i < 4096; i += 256) {
            int o = i >> 6, nl = i & 63;
            outb[(size_t)o * NTOK + n0 + nl] = __float2half_rn(stage[o * 64 + nl]);
        }
    }
}

// ---------------------------------------------------------------------------
// Flash cross-attention, fp16 mma, cp.async double-buffered K/V, MUFU exp2.
// grid (N/64, B, 2), block 256, 2 CTAs/SM. 3 barriers/iter.
// All logits are in the log2 domain (Q pre-scaled); softmax uses ex2.approx.
// ---------------------------------------------------------------------------
#define RSTR 36                               // u32 (half2) per smem row
#define VT_BYTES 36864                        // 256 x 36 x 4
#define K_BYTES  9216                         // 64 x 36 x 4
#define OFF_VT0 0
#define OFF_VT1 36864
#define OFF_K0  73728
#define OFF_K1  82944
#define OFF_Q   92160
#define OFF_P   101376
#define OFF_MX  110592
#define OFF_RS  110848
#define OFF_SC  111360
#define OFF_MH  111616
#define OFF_MC  112128
#define OFF_IV  112384
#define ATTN_SMEM 112640

__global__ __launch_bounds__(256, 2) void attn_kernel(
    const float* __restrict__ x1, const float* __restrict__ x2,
    const float* __restrict__ gamma_p, float* __restrict__ out)
{
    extern __shared__ char smem[];
    uint32_t sb = (uint32_t)__cvta_generic_to_shared(smem);

    uint32_t* Q2  = (uint32_t*)(smem + OFF_Q);
    uint32_t* P2  = (uint32_t*)(smem + OFF_P);
    float* rowmax = (float*)(smem + OFF_MX);
    float* rs     = (float*)(smem + OFF_RS);
    float* scl    = (float*)(smem + OFF_SC);
    float* mxh    = (float*)(smem + OFF_MH);
    float* mxcur  = (float*)(smem + OFF_MC);
    float* inv    = (float*)(smem + OFF_IV);

    int qtile = blockIdx.x, b = blockIdx.y, dir = blockIdx.z;
    int srckv = dir ^ 1;
    const float* xq = dir ? x2 : x1;
    int n0 = qtile * 64;

    int t    = threadIdx.x;
    int warp = t >> 5, lane = t & 31;
    int g    = lane >> 2, tig = lane & 3;
    int wr   = warp >> 1, wc = warp & 1;
    int qb   = wr * 16;
    int cb   = warp * 32;
    int r0   = qb + g, r1 = qb + g + 8;

    const float4* kg4 = (const float4*)&g_kh[srckv][b][0][0];
    const float4* vg4 = (const float4*)&g_vth[srckv][b][0][0];

    // ---- prologue: Q tile; prefetch tile 0 ----
    {
        const float4* qg4 = (const float4*)&g_qh[dir][b][n0][0];
        #pragma unroll
        for (int j = 0; j < 2; j++) {
            int i = t + 256 * j;
            int row = i >> 3, ch = i & 7;
            *(float4*)(smem + OFF_Q + row * (RSTR * 4) + ch * 16) = qg4[i];
        }
    }
    {
        #pragma unroll
        for (int j = 0; j < 2; j++) {
            int i = t + 256 * j;
            int row = i >> 3, ch = i & 7;
            cp16(sb + OFF_K0 + row * (RSTR * 4) + ch * 16, kg4 + i);
        }
        #pragma unroll
        for (int j = 0; j < 8; j++) {
            int i = t + 256 * j;
            int c = i >> 3, ch = i & 7;
            cp16(sb + OFF_VT0 + c * (RSTR * 4) + ch * 16, vg4 + (size_t)c * 512 + ch);
        }
        asm volatile("cp.async.commit_group;" ::: "memory");
    }
    if (t < 64) { rowmax[t] = -1e30f; mxcur[t] = -1e30f; }
    if (t < 128) rs[t] = 0.f;
    float oacc[16][4] = {};

    for (int it = 0; it < NTOK / 64; it++) {
        uint32_t* K2  = (uint32_t*)(smem + OFF_K0  + (it & 1) * K_BYTES);
        uint32_t* VT2 = (uint32_t*)(smem + OFF_VT0 + (it & 1) * VT_BYTES);

        asm volatile("cp.async.wait_group 0;" ::: "memory");
        __syncthreads();   // A: tile it visible; prev iter fully done

        // ---- prefetch tile it+1 ----
        if (it < NTOK / 64 - 1) {
            int itn = it + 1;
            uint32_t kb = sb + OFF_K0  + (itn & 1) * K_BYTES;
            uint32_t vb = sb + OFF_VT0 + (itn & 1) * VT_BYTES;
            const float4* ks = kg4 + (size_t)itn * 512;
            #pragma unroll
            for (int j = 0; j < 2; j++) {
                int i = t + 256 * j;
                int row = i >> 3, ch = i & 7;
                cp16(kb + row * (RSTR * 4) + ch * 16, ks + i);
            }
            #pragma unroll
            for (int j = 0; j < 8; j++) {
                int i = t + 256 * j;
                int c = i >> 3, ch = i & 7;
                cp16(vb + c * (RSTR * 4) + ch * 16,
                     vg4 + (size_t)c * 512 + itn * 8 + ch);
            }
            asm volatile("cp.async.commit_group;" ::: "memory");
        }

        // ---- S = Q K^T (fp16, log2 domain): warp = 16 q-rows x 32 m-cols ----
        float sf[4][4] = {};
        #pragma unroll
        for (int kk = 0; kk < 4; kk++) {
            int k0 = kk * 8;
            uint32_t a0 = Q2[r0 * RSTR + k0 + tig];
            uint32_t a1 = Q2[r1 * RSTR + k0 + tig];
            uint32_t a2 = Q2[r0 * RSTR + k0 + tig + 4];
            uint32_t a3 = Q2[r1 * RSTR + k0 + tig + 4];
            #pragma unroll
            for (int nb = 0; nb < 4; nb++) {
                int m = wc * 32 + nb * 8;
                uint32_t b0 = K2[(m + g) * RSTR + k0 + tig];
                uint32_t b1 = K2[(m + g) * RSTR + k0 + tig + 4];
                mma_fp16(sf[nb], a0, a1, a2, a3, b0, b1);
            }
        }
        // local (half-row) max
        {
            float lm0 = -1e30f, lm1 = -1e30f;
            #pragma unroll
            for (int nb = 0; nb < 4; nb++) {
                lm0 = fmaxf(lm0, fmaxf(sf[nb][0], sf[nb][1]));
                lm1 = fmaxf(lm1, fmaxf(sf[nb][2], sf[nb][3]));
            }
            lm0 = fmaxf(lm0, __shfl_xor_sync(0xffffffffu, lm0, 1));
            lm0 = fmaxf(lm0, __shfl_xor_sync(0xffffffffu, lm0, 2));
            lm1 = fmaxf(lm1, __shfl_xor_sync(0xffffffffu, lm1, 1));
            lm1 = fmaxf(lm1, __shfl_xor_sync(0xffffffffu, lm1, 2));
            if (tig == 0) { mxh[wc * 64 + r0] = lm0; mxh[wc * 64 + r1] = lm1; }
        }
        __syncthreads();   // M: cross-half maxima visible

        // ---- online softmax: P = 2^(s - newmax) via MUFU ex2 ----
        {
            float om0 = rowmax[r0], om1 = rowmax[r1];
            float nm0 = fmaxf(om0, fmaxf(mxh[r0], mxh[64 + r0]));
            float nm1 = fmaxf(om1, fmaxf(mxh[r1], mxh[64 + r1]));
            float ps0 = 0.f, ps1 = 0.f;
            #pragma unroll
            for (int nb = 0; nb < 4; nb++) {
                float p0 = ex2f(sf[nb][0] - nm0);
                float p1 = ex2f(sf[nb][1] - nm0);
                float p2 = ex2f(sf[nb][2] - nm1);
                float p3 = ex2f(sf[nb][3] - nm1);
                ps0 += p0 + p1;
                ps1 += p2 + p3;
                int col2 = wc * 16 + nb * 4 + tig;
                P2[r0 * RSTR + col2] = h2_of(p0, p1);
                P2[r1 * RSTR + col2] = h2_of(p2, p3);
            }
            ps0 += __shfl_xor_sync(0xffffffffu, ps0, 1);
            ps0 += __shfl_xor_sync(0xffffffffu, ps0, 2);
            ps1 += __shfl_xor_sync(0xffffffffu, ps1, 1);
            ps1 += __shfl_xor_sync(0xffffffffu, ps1, 2);
            if (tig == 0) {
                rs[wc * 64 + r0] = rs[wc * 64 + r0] * ex2f(om0 - nm0) + ps0;
                rs[wc * 64 + r1] = rs[wc * 64 + r1] * ex2f(om1 - nm1) + ps1;
                if (wc == 0) {
                    scl[r0] = ex2f(om0 - nm0);
                    scl[r1] = ex2f(om1 - nm1);
                    mxcur[r0] = nm0;
                    mxcur[r1] = nm1;
                }
            }
        }
        __syncthreads();   // P: P + scl visible

        // race-free rowmax publish (read next iter after barrier M)
        if (t < 64) rowmax[t] = mxcur[t];

        // ---- O rescale (max updates nearly every tile; unconditional) ----
        #pragma unroll
        for (int nb = 0; nb < 8; nb++) {
            int q = nb * 8 + tig * 2;
            float2 sc = *(float2*)&scl[q];
            oacc[nb][0] *= sc.x; oacc[nb][1] *= sc.y;
            oacc[nb][2] *= sc.x; oacc[nb][3] *= sc.y;
            oacc[8 + nb][0] *= sc.x; oacc[8 + nb][1] *= sc.y;
            oacc[8 + nb][2] *= sc.x; oacc[8 + nb][3] *= sc.y;
        }

        // ---- O^T += V^T P^T (fp16): warp = 32 c-rows x 64 q-cols ----
        #pragma unroll
        for (int kk = 0; kk < 4; kk++) {
            int k0 = kk * 8;
            uint32_t a00 = VT2[(cb + g)      * RSTR + k0 + tig];
            uint32_t a01 = VT2[(cb + g + 8)  * RSTR + k0 + tig];
            uint32_t a02 = VT2[(cb + g)      * RSTR + k0 + tig + 4];
            uint32_t a03 = VT2[(cb + g + 8)  * RSTR + k0 + tig + 4];
            uint32_t a10 = VT2[(cb + g + 16) * RSTR + k0 + tig];
            uint32_t a11 = VT2[(cb + g + 24) * RSTR + k0 + tig];
            uint32_t a12 = VT2[(cb + g + 16) * RSTR + k0 + tig + 4];
            uint32_t a13 = VT2[(cb + g + 24) * RSTR + k0 + tig + 4];
            #pragma unroll
            for (int nb = 0; nb < 8; nb++) {
                uint32_t b0 = P2[(nb * 8 + g) * RSTR + k0 + tig];
                uint32_t b1 = P2[(nb * 8 + g) * RSTR + k0 + tig + 4];
                mma_fp16(oacc[nb],     a00, a01, a02, a03, b0, b1);
                mma_fp16(oacc[8 + nb], a10, a11, a12, a13, b0, b1);
            }
        }
        // no trailing barrier: next iter's barA orders everything
    }

    // ---- epilogue: normalize + residual, direct float2 stores ----
    __syncthreads();
    if (t < 64) inv[t] = 1.f / (rs[t] + rs[64 + t]);
    __syncthreads();

    float gm = gamma_p[0];
    size_t obase = ((size_t)(dir * BATCH + b)) * CDIM * NTOK;
    const float* xb = xq + (size_t)b * CDIM * NTOK;

    #pragma unroll
    for (int nb = 0; nb < 8; nb++) {
        int q = nb * 8 + tig * 2;
        float2 iv = *(float2*)&inv[q];
        int crows[4] = { cb + g, cb + g + 8, cb + g + 16, cb + g + 24 };
        float ox[4][2] = {
            { oacc[nb][0],     oacc[nb][1]     },
            { oacc[nb][2],     oacc[nb][3]     },
            { oacc[8 + nb][0], oacc[8 + nb][1] },
            { oacc[8 + nb][2], oacc[8 + nb][3] },
        };
        #pragma unroll
        for (int rr = 0; rr < 4; rr++) {
            size_t idx = (size_t)crows[rr] * NTOK + n0 + q;
            float2 xv = *(const float2*)&xb[idx];
            float2 ov;
            ov.x = xv.x + gm * iv.x * ox[rr][0];
            ov.y = xv.y + gm * iv.y * ox[rr][1];
            *(float2*)&out[obase + idx] = ov;
        }
    }
}

extern "C" void kernel_launch(void* const* d_in, const int* in_sizes, int n_in,
                              void* d_out, int out_size)
{
    const float* x1    = (const float*)d_in[0];
    const float* x2    = (const float*)d_in[1];
    const float* Wq    = (const float*)d_in[2];
    const float* bq    = (const float*)d_in[3];
    const float* Wk    = (const float*)d_in[4];
    const float* bk    = (const float*)d_in[5];
    const float* Wv    = (const float*)d_in[6];
    const float* bv    = (const float*)d_in[7];
    const float* gamma = (const float*)d_in[8];
    float* out = (float*)d_out;
    (void)in_sizes; (void)n_in; (void)out_size;

    cudaFuncSetAttribute(attn_kernel, cudaFuncAttributeMaxDynamicSharedMemorySize,
                         ATTN_SMEM);

    proj_kernel<<<dim3(NTOK / 64, 6, 2 * BATCH), 256>>>(x1, x2, Wq, bq, Wk, bk, Wv, bv);
    attn_kernel<<<dim3(NTOK / 64, BATCH, 2), 256, ATTN_SMEM>>>(x1, x2, gamma, out);
}